// round 16
// baseline (speedup 1.0000x reference)
#include <cuda_runtime.h>
#include <cuda_fp16.h>
#include <math.h>
#include <stdint.h>

// Problem constants (fixed shapes)
#define NN   4096      // N = V*B
#define BB   2048      // batch
#define VV   2         // views
#define DD   256       // feature dim
#define CC   1000      // classes
#define TEMP 0.07f
#define NTILE 32       // 4096 / 128
#define NBLK  (NTILE * (NTILE + 1) / 2)   // 528 triangular tiles
#define MGRID 264      // persistent CTAs: each does exactly 2 tiles (co-resident)

// Scratch (no cudaMalloc allowed)
__device__ __half g_f16[NN * DD];         // fp16 normalized features, view-major
__device__ float g_mod[BB];               // focal modulation per sample
__device__ float g_S[NN];                 // sum exp(l - M) over j != i
__device__ float g_P[NN];                 // sum over positives of (l - M)
__device__ float g_cnt[NN];               // positive counts
__device__ unsigned g_done;               // completion counter (finalize gate)
__device__ unsigned g_arrive;             // norm-phase device-wide barrier

// ============================================================================
// PTX helpers (valid on compute_103 base target)
// ============================================================================
__device__ __forceinline__ uint32_t smem_to_u32(const void* p) {
    uint32_t a;
    asm("{ .reg .u64 t; cvta.to.shared.u64 t, %1; cvt.u32.u64 %0, t; }"
        : "=r"(a) : "l"(p));
    return a;
}
#define SMEM_SWIZZLE_128B(byte_offset) \
    ((byte_offset) ^ (((byte_offset) >> 3) & 0x70))

__device__ __forceinline__ float ex2_approx(float x) {
    float r;
    asm("ex2.approx.ftz.f32 %0, %1;" : "=f"(r) : "f"(x));
    return r;
}

// mma.sync fp16 (sm_70+): D(16x8 f32) += A(16x16 f16) * B(16x8 f16)
#define MMA_F16(d, a, b0, b1) \
    asm volatile("mma.sync.aligned.m16n8k16.row.col.f32.f16.f16.f32 " \
        "{%0,%1,%2,%3}, {%4,%5,%6,%7}, {%8,%9}, {%0,%1,%2,%3};" \
        : "+f"((d)[0]), "+f"((d)[1]), "+f"((d)[2]), "+f"((d)[3]) \
        : "r"((a)[0]), "r"((a)[1]), "r"((a)[2]), "r"((a)[3]), \
          "r"(b0), "r"(b1))

#define LDSM_X4(r0, r1, r2, r3, addr) \
    asm volatile("ldmatrix.sync.aligned.m8n8.x4.shared.b16 {%0,%1,%2,%3}, [%4];" \
        : "=r"(r0), "=r"(r1), "=r"(r2), "=r"(r3) : "r"(addr))

#define CP_ASYNC_16(dst, src) \
    asm volatile("cp.async.cg.shared.global [%0], [%1], 16;" \
        :: "r"(dst), "l"(src) : "memory")
#define CP_ASYNC_COMMIT() asm volatile("cp.async.commit_group;" ::: "memory")
#define CP_ASYNC_WAIT(n)  asm volatile("cp.async.wait_group %0;" :: "n"(n) : "memory")

// ---------------------------------------------------------------------------
// Main persistent kernel. Phases:
//  0. normalize 16 rows per CTA -> g_f16; zero g_S slice; device-wide barrier
//     (legal: all 264 CTAs are co-resident, 2 CTAs/SM x 148 SMs = 296 slots).
//  1. symmetric fp16 HMMA Gram GEMM, 2 static tiles per CTA, 3-stage
//     cp.async pipeline (one sync per chunk), cross-tile chunk prefetch.
//     Epilogue: S only, single-EX2, diag/off-diag specialized.
//  2. tail shadow: focal modulation + class-sum P/cnt.
//  3. last CTA: final loss reduction; resets counters for graph replay.
// ---------------------------------------------------------------------------
#define OFF_A 0
#define OFF_B 16384
#define STAGE_BYTES 32768
#define DYN_SMEM (3 * STAGE_BYTES + 1024)

__device__ __forceinline__ void load_tile_async(uint32_t dstb, const __half* src,
                                                int row0, int kc, int tid) {
    // 128 rows x 64 halfs (128 B) per tile = 1024 16B segments
#pragma unroll
    for (int it = 0; it < 4; ++it) {
        int seg = tid + it * 256;
        int r = seg >> 3, sc = seg & 7;
        const void* g = src + (size_t)(row0 + r) * DD + kc * 64 + sc * 8;
        uint32_t off = (uint32_t)(r * 128 + sc * 16);
        CP_ASYNC_16(dstb + SMEM_SWIZZLE_128B(off), g);
    }
}

__device__ __forceinline__ void tri_decode(int t, int& i0, int& j0) {
    int bi = 0, rem = t;
    while (rem >= NTILE - bi) { rem -= NTILE - bi; ++bi; }
    i0 = bi * 128;
    j0 = (bi + rem) * 128;
}

// Epilogue for one 128x128 tile. DIAG: skip self-pairs, no column side.
template <bool DIAG>
__device__ __forceinline__ void tile_epilogue(
    float acc[4][4][4], int i0, int j0, int wm, int wn, int lane, int tid,
    float* sSr, float* sSc)
{
    const float c1 = (1.0f / TEMP) * 1.4426950408889634f;   // invT * log2(e)
    const float c0 = -c1;
    const int g  = lane >> 2;
    const int t2 = (lane & 3) * 2;
    float rs[4][2];
#pragma unroll
    for (int mf = 0; mf < 4; ++mf)
#pragma unroll
        for (int h = 0; h < 2; ++h) rs[mf][h] = 0.f;

#pragma unroll
    for (int nf = 0; nf < 4; ++nf) {
        const int cb = wn * 32 + nf * 8 + t2;   // local cols cb, cb+1
        float cs[2] = {0.f, 0.f};
#pragma unroll
        for (int mf = 0; mf < 4; ++mf) {
            const int r0 = wm * 64 + mf * 16 + g;
#pragma unroll
            for (int h = 0; h < 2; ++h) {
#pragma unroll
                for (int q = 0; q < 2; ++q) {
                    float e = ex2_approx(fmaf(acc[mf][nf][h * 2 + q], c1, c0));
                    if (DIAG) {
                        if (i0 + r0 + h * 8 == j0 + cb + q) e = 0.f;
                        rs[mf][h] += e;
                    } else {
                        rs[mf][h] += e;
                        cs[q]     += e;
                    }
                }
            }
        }
        if (!DIAG) {
#pragma unroll
            for (int o = 4; o <= 16; o <<= 1) {
                cs[0] += __shfl_xor_sync(0xffffffffu, cs[0], o);
                cs[1] += __shfl_xor_sync(0xffffffffu, cs[1], o);
            }
            if (g == 0) {
                atomicAdd(&sSc[cb], cs[0]);
                atomicAdd(&sSc[cb + 1], cs[1]);
            }
        }
    }
#pragma unroll
    for (int mf = 0; mf < 4; ++mf) {
        const int r0 = wm * 64 + mf * 16 + g;
#pragma unroll
        for (int h = 0; h < 2; ++h) {
#pragma unroll
            for (int o = 1; o <= 2; o <<= 1)
                rs[mf][h] += __shfl_xor_sync(0xffffffffu, rs[mf][h], o);
        }
        if ((lane & 3) == 0) {
            atomicAdd(&sSr[r0], rs[mf][0]);
            atomicAdd(&sSr[r0 + 8], rs[mf][1]);
        }
    }
    __syncthreads();
    if (tid < 128) {
        atomicAdd(&g_S[i0 + tid], sSr[tid]);
        if (!DIAG) atomicAdd(&g_S[j0 + tid], sSc[tid]);
        sSr[tid] = 0.f;               // re-arm for next tile
        sSc[tid] = 0.f;
    }
}

__global__ void __launch_bounds__(256, 2) main_kernel(const float* __restrict__ feats,
                                                      const float* __restrict__ preds,
                                                      const int* __restrict__ labels,
                                                      float* __restrict__ out) {
    extern __shared__ char dsm[];
    __shared__ float sSr[128], sSc[128];
    __shared__ float red[256];
    __shared__ __align__(16) float Z[DD];
    __shared__ __align__(16) int zlist[64];
    __shared__ int zm;
    __shared__ unsigned isLast;

    const int tid  = threadIdx.x;
    const int w    = tid >> 5;
    const int lane = tid & 31;

    uint32_t dsm_u = smem_to_u32(dsm);
    uint32_t sb    = (dsm_u + 1023u) & ~1023u;

    const float invT = 1.0f / TEMP;
    const int wm = w >> 2;          // 0..1 -> rows wm*64..+63
    const int wn = w & 3;           // 0..3 -> cols wn*32..+31

    // ============ Phase 0: fused normalization (16 rows per CTA) ============
    {
        int base = blockIdx.x * 16;
#pragma unroll
        for (int rr = 0; rr < 2; ++rr) {
            int gw = base + rr * 8 + w;
            if (gw < NN) {
                int b = gw & (BB - 1);
                int v = gw >> 11;
                const float4* src = reinterpret_cast<const float4*>(
                    feats + (size_t)(b * VV + v) * DD);
                float4 x0 = src[lane];
                float4 x1 = src[lane + 32];
                float ss = x0.x*x0.x + x0.y*x0.y + x0.z*x0.z + x0.w*x0.w
                         + x1.x*x1.x + x1.y*x1.y + x1.z*x1.z + x1.w*x1.w;
#pragma unroll
                for (int o = 16; o > 0; o >>= 1) ss += __shfl_xor_sync(0xffffffffu, ss, o);
                float inv = rsqrtf(ss);
                __half2 h0 = __floats2half2_rn(x0.x * inv, x0.y * inv);
                __half2 h1 = __floats2half2_rn(x0.z * inv, x0.w * inv);
                __half2 h2 = __floats2half2_rn(x1.x * inv, x1.y * inv);
                __half2 h3 = __floats2half2_rn(x1.z * inv, x1.w * inv);
                __half2* hp = reinterpret_cast<__half2*>(g_f16 + (size_t)gw * DD);
                hp[2 * lane]          = h0;
                hp[2 * lane + 1]      = h1;
                hp[64 + 2 * lane]     = h2;
                hp[64 + 2 * lane + 1] = h3;
                if (lane == 0) g_S[gw] = 0.f;
            }
        }
        // device-wide barrier (all MGRID CTAs are co-resident)
        __threadfence();
        __syncthreads();
        if (tid == 0) {
            atomicAdd(&g_arrive, 1u);
            volatile unsigned* va = &g_arrive;
            while (*va < MGRID) { }
        }
        __syncthreads();
        __threadfence();
    }

    // ============ Phase 1: GEMM (static 2 tiles per CTA) ============
    int ti0[2], tj0[2];
    tri_decode(blockIdx.x,         ti0[0], tj0[0]);
    tri_decode(blockIdx.x + MGRID, ti0[1], tj0[1]);

    if (tid < 128) { sSr[tid] = 0.f; sSc[tid] = 0.f; }

    // pipeline prologue: chunks 0, 1 (global chunk id g: tile g>>2, kc g&3)
    load_tile_async(sb + 0 * STAGE_BYTES + OFF_A, g_f16, ti0[0], 0, tid);
    load_tile_async(sb + 0 * STAGE_BYTES + OFF_B, g_f16, tj0[0], 0, tid);
    CP_ASYNC_COMMIT();
    load_tile_async(sb + 1 * STAGE_BYTES + OFF_A, g_f16, ti0[0], 1, tid);
    load_tile_async(sb + 1 * STAGE_BYTES + OFF_B, g_f16, tj0[0], 1, tid);
    CP_ASYNC_COMMIT();

    float acc[4][4][4];
#pragma unroll
    for (int mf = 0; mf < 4; ++mf)
#pragma unroll
        for (int nf = 0; nf < 4; ++nf)
#pragma unroll
            for (int q = 0; q < 4; ++q) acc[mf][nf][q] = 0.f;

    for (int g = 0; g < 8; ++g) {
        if (g < 7) { CP_ASYNC_WAIT(1); } else { CP_ASYNC_WAIT(0); }
        __syncthreads();                      // chunk g ready

        if (g + 2 < 8) {                      // prefetch into retired stage
            int gn = g + 2;
            uint32_t stn = sb + (gn % 3) * STAGE_BYTES;
            load_tile_async(stn + OFF_A, g_f16, ti0[gn >> 2], gn & 3, tid);
            load_tile_async(stn + OFF_B, g_f16, tj0[gn >> 2], gn & 3, tid);
            CP_ASYNC_COMMIT();
        }

        const uint32_t stb = sb + (g % 3) * STAGE_BYTES;
#pragma unroll
        for (int ks = 0; ks < 4; ++ks) {
            uint32_t ah[4][4];
#pragma unroll
            for (int mf = 0; mf < 4; ++mf) {
                int row  = wm * 64 + mf * 16 + (lane & 15);
                int koff = ks * 16 + ((lane >> 4) << 3);
                uint32_t byoff = SMEM_SWIZZLE_128B((uint32_t)(row * 128 + koff * 2));
                LDSM_X4(ah[mf][0], ah[mf][1], ah[mf][2], ah[mf][3], stb + OFF_A + byoff);
            }
#pragma unroll
            for (int nf2 = 0; nf2 < 2; ++nf2) {
                int brow = wn * 32 + nf2 * 16 + (lane & 7) + ((lane >> 4) << 3);
                int bk   = ks * 16 + (((lane >> 3) & 1) << 3);
                uint32_t boff = SMEM_SWIZZLE_128B((uint32_t)(brow * 128 + bk * 2));
                uint32_t bh[4];
                LDSM_X4(bh[0], bh[1], bh[2], bh[3], stb + OFF_B + boff);
#pragma unroll
                for (int mf = 0; mf < 4; ++mf) {
                    MMA_F16(acc[mf][2*nf2],   ah[mf], bh[0], bh[1]);
                    MMA_F16(acc[mf][2*nf2+1], ah[mf], bh[2], bh[3]);
                }
            }
        }

        if ((g & 3) == 3) {                   // tile complete -> epilogue
            int t = g >> 2;
            if (ti0[t] == tj0[t])
                tile_epilogue<true >(acc, ti0[t], tj0[t], wm, wn, lane, tid, sSr, sSc);
            else
                tile_epilogue<false>(acc, ti0[t], tj0[t], wm, wn, lane, tid, sSr, sSc);
#pragma unroll
            for (int mf = 0; mf < 4; ++mf)
#pragma unroll
                for (int nf = 0; nf < 4; ++nf)
#pragma unroll
                    for (int q = 0; q < 4; ++q) acc[mf][nf][q] = 0.f;
        }
    }

    // ============ Phase 2a: focal modulation (warp-per-sample) ============
    {
        int b = blockIdx.x * 8 + w;        // 2112 warps cover 2048 samples
        if (b < BB) {
            const float4* row4 = reinterpret_cast<const float4*>(preds + (size_t)b * CC);
            float s = 0.f;
#pragma unroll
            for (int k = 0; k < 8; ++k) {
                int idx = lane + 32 * k;
                if (idx < CC / 4) {
                    float4 v = row4[idx];
                    s += __expf(v.x) + __expf(v.y) + __expf(v.z) + __expf(v.w);
                }
            }
#pragma unroll
            for (int o = 16; o > 0; o >>= 1) s += __shfl_xor_sync(0xffffffffu, s, o);
            if (lane == 0) {
                float pl = preds[(size_t)b * CC + labels[b]];
                float pt = __expf(pl) / s;
                float om = 1.f - pt;
                g_mod[b] = om * om;
            }
        }
    }

    // ============ Phase 2b: zpk (class sums -> P, cnt) ============
    for (int c = blockIdx.x; c < CC; c += MGRID) {
        __syncthreads();
        if (tid == 0) zm = 0;
        __syncthreads();
        for (int b = tid; b < BB; b += 256)
            if (labels[b] == c) { int p = atomicAdd(&zm, 1); if (p < 64) zlist[p] = b; }
        __syncthreads();
        const int mm = zm < 64 ? zm : 64;

        float z = 0.f;
        for (int q = 0; q < mm; ++q) {
            int b = zlist[q];
            z += __half2float(g_f16[(size_t)b * DD + tid])
               + __half2float(g_f16[(size_t)(BB + b) * DD + tid]);
        }
        Z[tid] = z;
        __syncthreads();

        const float cnt = 2.f * (float)zm - 1.f;
        for (int r = w; r < 2 * mm; r += 8) {
            int b = zlist[r >> 1];
            int row = (r & 1) ? (BB + b) : b;
            const __half2* hp = reinterpret_cast<const __half2*>(g_f16 + (size_t)row * DD);
            const float2*  zp = reinterpret_cast<const float2*>(Z);
            float dot = 0.f, self = 0.f;
#pragma unroll
            for (int k = 0; k < 4; ++k) {
                float2 hv = __half22float2(hp[lane + 32 * k]);
                float2 zv = zp[lane + 32 * k];
                dot  += hv.x * zv.x + hv.y * zv.y;
                self += hv.x * hv.x + hv.y * hv.y;
            }
#pragma unroll
            for (int o = 16; o > 0; o >>= 1) {
                dot  += __shfl_xor_sync(0xffffffffu, dot, o);
                self += __shfl_xor_sync(0xffffffffu, self, o);
            }
            if (lane == 0) {
                g_P[row]   = (dot - self - cnt) * invT;
                g_cnt[row] = cnt;
            }
        }
    }

    // ============ Phase 3: fused finalize (last block) ============
    __threadfence();
    __syncthreads();
    if (tid == 0) isLast = (atomicAdd(&g_done, 1u) == MGRID - 1) ? 1u : 0u;
    __syncthreads();
    if (isLast) {
        __threadfence();
        float accv = 0.f;
        for (int i = tid; i < NN; i += 256) {
            float Sv = __ldcg(&g_S[i]);
            float Pv = __ldcg(&g_P[i]);
            float Cv = __ldcg(&g_cnt[i]);
            float mv = __ldcg(&g_mod[i & (BB - 1)]);
            accv += mv * (Pv / Cv - logf(Sv));
        }
        red[tid] = accv;
        __syncthreads();
#pragma unroll
        for (int s = 128; s > 0; s >>= 1) {
            if (tid < s) red[tid] += red[tid + s];
            __syncthreads();
        }
        if (tid == 0) {
            out[0] = -red[0] / (float)NN;
            g_done = 0u;          // reset counters for the next graph replay
            g_arrive = 0u;
        }
    }
}

// ---------------------------------------------------------------------------
extern "C" void kernel_launch(void* const* d_in, const int* in_sizes, int n_in,
                              void* d_out, int out_size) {
    const float* feats  = (const float*)d_in[0];   // [B, V, D]
    const float* preds  = (const float*)d_in[1];   // [B, C]
    const int*   labels = (const int*)d_in[2];     // [B]
    float* out = (float*)d_out;

    cudaFuncSetAttribute(main_kernel, cudaFuncAttributeMaxDynamicSharedMemorySize, DYN_SMEM);

    main_kernel<<<MGRID, 256, DYN_SMEM>>>(feats, preds, labels, out);
}

// round 17
// speedup vs baseline: 1.0557x; 1.0557x over previous
#include <cuda_runtime.h>
#include <cuda_fp16.h>
#include <math.h>
#include <stdint.h>

// Problem constants (fixed shapes)
#define NN   4096      // N = V*B
#define BB   2048      // batch
#define VV   2         // views
#define DD   256       // feature dim
#define CC   1000      // classes
#define TEMP 0.07f
#define NTILE 32       // 4096 / 128
#define NBLK  (NTILE * (NTILE + 1) / 2)   // 528 triangular tiles
#define MGRID 264      // persistent CTAs: each does exactly 2 tiles

// Scratch (no cudaMalloc allowed)
__device__ __half g_f16[NN * DD];         // fp16 normalized features, view-major
__device__ float g_mod[BB];               // focal modulation per sample
__device__ float g_S[NN];                 // sum exp(l - M) over j != i
__device__ float g_P[NN];                 // sum over positives of (l - M)
__device__ float g_cnt[NN];               // positive counts
__device__ unsigned g_done;               // main-kernel completion counter

// ============================================================================
// PTX helpers (valid on compute_103 base target)
// ============================================================================
__device__ __forceinline__ uint32_t smem_to_u32(const void* p) {
    uint32_t a;
    asm("{ .reg .u64 t; cvta.to.shared.u64 t, %1; cvt.u32.u64 %0, t; }"
        : "=r"(a) : "l"(p));
    return a;
}
#define SMEM_SWIZZLE_128B(byte_offset) \
    ((byte_offset) ^ (((byte_offset) >> 3) & 0x70))

__device__ __forceinline__ float ex2_approx(float x) {
    float r;
    asm("ex2.approx.ftz.f32 %0, %1;" : "=f"(r) : "f"(x));
    return r;
}

// mma.sync fp16 (sm_70+): D(16x8 f32) += A(16x16 f16) * B(16x8 f16)
#define MMA_F16(d, a, b0, b1) \
    asm volatile("mma.sync.aligned.m16n8k16.row.col.f32.f16.f16.f32 " \
        "{%0,%1,%2,%3}, {%4,%5,%6,%7}, {%8,%9}, {%0,%1,%2,%3};" \
        : "+f"((d)[0]), "+f"((d)[1]), "+f"((d)[2]), "+f"((d)[3]) \
        : "r"((a)[0]), "r"((a)[1]), "r"((a)[2]), "r"((a)[3]), \
          "r"(b0), "r"(b1))

#define LDSM_X4(r0, r1, r2, r3, addr) \
    asm volatile("ldmatrix.sync.aligned.m8n8.x4.shared.b16 {%0,%1,%2,%3}, [%4];" \
        : "=r"(r0), "=r"(r1), "=r"(r2), "=r"(r3) : "r"(addr))

#define CP_ASYNC_16(dst, src) \
    asm volatile("cp.async.cg.shared.global [%0], [%1], 16;" \
        :: "r"(dst), "l"(src) : "memory")
#define CP_ASYNC_COMMIT() asm volatile("cp.async.commit_group;" ::: "memory")
#define CP_ASYNC_WAIT(n)  asm volatile("cp.async.wait_group %0;" :: "n"(n) : "memory")

// ---------------------------------------------------------------------------
// K0 (norm): normalize rows + view-major restack -> fp16; zero S accumulator.
// ---------------------------------------------------------------------------
__global__ void __launch_bounds__(256) norm_kernel(const float* __restrict__ feats) {
    const int tid = threadIdx.x, lane = tid & 31, w = tid >> 5;
    int gw = blockIdx.x * 8 + w;
    int b = gw & (BB - 1);
    int v = gw >> 11;

    const float4* src = reinterpret_cast<const float4*>(feats + (size_t)(b * VV + v) * DD);
    float4 x0 = src[lane];
    float4 x1 = src[lane + 32];

    float ss = x0.x*x0.x + x0.y*x0.y + x0.z*x0.z + x0.w*x0.w
             + x1.x*x1.x + x1.y*x1.y + x1.z*x1.z + x1.w*x1.w;
#pragma unroll
    for (int o = 16; o > 0; o >>= 1) ss += __shfl_xor_sync(0xffffffffu, ss, o);
    float inv = rsqrtf(ss);

    __half2 h0 = __floats2half2_rn(x0.x * inv, x0.y * inv);
    __half2 h1 = __floats2half2_rn(x0.z * inv, x0.w * inv);
    __half2 h2 = __floats2half2_rn(x1.x * inv, x1.y * inv);
    __half2 h3 = __floats2half2_rn(x1.z * inv, x1.w * inv);

    __half2* hp = reinterpret_cast<__half2*>(g_f16 + (size_t)gw * DD);
    hp[2 * lane]          = h0;
    hp[2 * lane + 1]      = h1;
    hp[64 + 2 * lane]     = h2;
    hp[64 + 2 * lane + 1] = h3;

    if (lane == 0) g_S[gw] = 0.f;
}

// ---------------------------------------------------------------------------
// K1 (main): persistent symmetric fp16 HMMA Gram GEMM; 264 CTAs x 2 tiles,
// flattened 8-chunk 3-stage cp.async pipeline, ONE sync per chunk.
// Inner loop: B-first, A-streamed (lower max-live regs, LDSM/MMA overlap).
// Epilogue: S only, single-EX2 exp, diag/off-diag specialized.
// Post-GEMM (tail shadow): focal modulation + class-sum P/cnt; last CTA
// finalizes the loss.
// ---------------------------------------------------------------------------
#define OFF_A 0
#define OFF_B 16384
#define STAGE_BYTES 32768
#define DYN_SMEM (3 * STAGE_BYTES + 1024)

__device__ __forceinline__ void load_tile_async(uint32_t dstb, const __half* src,
                                                int row0, int kc, int tid) {
    // 128 rows x 64 halfs (128 B) per tile = 1024 16B segments
#pragma unroll
    for (int it = 0; it < 4; ++it) {
        int seg = tid + it * 256;
        int r = seg >> 3, sc = seg & 7;
        const void* g = src + (size_t)(row0 + r) * DD + kc * 64 + sc * 8;
        uint32_t off = (uint32_t)(r * 128 + sc * 16);
        CP_ASYNC_16(dstb + SMEM_SWIZZLE_128B(off), g);
    }
}

__device__ __forceinline__ void tri_decode(int t, int& i0, int& j0) {
    int bi = 0, rem = t;
    while (rem >= NTILE - bi) { rem -= NTILE - bi; ++bi; }
    i0 = bi * 128;
    j0 = (bi + rem) * 128;
}

// Epilogue for one 128x128 tile. DIAG: skip self-pairs, no column side.
template <bool DIAG>
__device__ __forceinline__ void tile_epilogue(
    float acc[4][4][4], int i0, int j0, int wm, int wn, int lane, int tid,
    float* sSr, float* sSc)
{
    const float c1 = (1.0f / TEMP) * 1.4426950408889634f;   // invT * log2(e)
    const float c0 = -c1;
    const int g  = lane >> 2;
    const int t2 = (lane & 3) * 2;
    float rs[4][2];
#pragma unroll
    for (int mf = 0; mf < 4; ++mf)
#pragma unroll
        for (int h = 0; h < 2; ++h) rs[mf][h] = 0.f;

#pragma unroll
    for (int nf = 0; nf < 4; ++nf) {
        const int cb = wn * 32 + nf * 8 + t2;   // local cols cb, cb+1
        float cs[2] = {0.f, 0.f};
#pragma unroll
        for (int mf = 0; mf < 4; ++mf) {
            const int r0 = wm * 64 + mf * 16 + g;
#pragma unroll
            for (int h = 0; h < 2; ++h) {
#pragma unroll
                for (int q = 0; q < 2; ++q) {
                    float e = ex2_approx(fmaf(acc[mf][nf][h * 2 + q], c1, c0));
                    if (DIAG) {
                        if (i0 + r0 + h * 8 == j0 + cb + q) e = 0.f;
                        rs[mf][h] += e;
                    } else {
                        rs[mf][h] += e;
                        cs[q]     += e;
                    }
                }
            }
        }
        if (!DIAG) {
#pragma unroll
            for (int o = 4; o <= 16; o <<= 1) {
                cs[0] += __shfl_xor_sync(0xffffffffu, cs[0], o);
                cs[1] += __shfl_xor_sync(0xffffffffu, cs[1], o);
            }
            if (g == 0) {
                atomicAdd(&sSc[cb], cs[0]);
                atomicAdd(&sSc[cb + 1], cs[1]);
            }
        }
    }
#pragma unroll
    for (int mf = 0; mf < 4; ++mf) {
        const int r0 = wm * 64 + mf * 16 + g;
#pragma unroll
        for (int h = 0; h < 2; ++h) {
#pragma unroll
            for (int o = 1; o <= 2; o <<= 1)
                rs[mf][h] += __shfl_xor_sync(0xffffffffu, rs[mf][h], o);
        }
        if ((lane & 3) == 0) {
            atomicAdd(&sSr[r0], rs[mf][0]);
            atomicAdd(&sSr[r0 + 8], rs[mf][1]);
        }
    }
    __syncthreads();
    if (tid < 128) {
        atomicAdd(&g_S[i0 + tid], sSr[tid]);
        if (!DIAG) atomicAdd(&g_S[j0 + tid], sSc[tid]);
        sSr[tid] = 0.f;               // re-arm for next tile
        sSc[tid] = 0.f;
    }
}

__global__ void __launch_bounds__(256, 2) main_kernel(const float* __restrict__ preds,
                                                      const int* __restrict__ labels,
                                                      float* __restrict__ out) {
    extern __shared__ char dsm[];
    __shared__ float sSr[128], sSc[128];
    __shared__ float red[256];
    __shared__ __align__(16) float Z[DD];
    __shared__ __align__(16) int zlist[64];
    __shared__ int zm;
    __shared__ unsigned isLast;

    const int tid  = threadIdx.x;
    const int w    = tid >> 5;
    const int lane = tid & 31;

    uint32_t dsm_u = smem_to_u32(dsm);
    uint32_t sb    = (dsm_u + 1023u) & ~1023u;

    const float invT = 1.0f / TEMP;
    const int wm = w >> 2;          // 0..1 -> rows wm*64..+63
    const int wn = w & 3;           // 0..3 -> cols wn*32..+31

    // Hoisted per-warp unswizzled fragment address components.
    // A: row = wm*64 + mf*16 + (lane&15); koff base = (lane>>4)*8 halves.
    const uint32_t a_row_part = (uint32_t)((wm * 64 + (lane & 15)) * 128
                                           + ((lane >> 4) << 3) * 2);
    // B: row = wn*32 + nf2*16 + (lane&7) + ((lane>>4)<<3); k base = ((lane>>3)&1)*8.
    const uint32_t b_row_part = (uint32_t)((wn * 32 + (lane & 7) + ((lane >> 4) << 3)) * 128
                                           + ((((lane >> 3) & 1)) << 3) * 2);

    // decode both tiles up front
    int ti0[2], tj0[2];
    tri_decode(blockIdx.x,         ti0[0], tj0[0]);
    tri_decode(blockIdx.x + MGRID, ti0[1], tj0[1]);

    if (tid < 128) { sSr[tid] = 0.f; sSc[tid] = 0.f; }

    // pipeline prologue: chunks 0, 1 (global chunk id g: tile g>>2, kc g&3)
    load_tile_async(sb + (0 % 3) * STAGE_BYTES + OFF_A, g_f16, ti0[0], 0, tid);
    load_tile_async(sb + (0 % 3) * STAGE_BYTES + OFF_B, g_f16, tj0[0], 0, tid);
    CP_ASYNC_COMMIT();
    load_tile_async(sb + (1 % 3) * STAGE_BYTES + OFF_A, g_f16, ti0[0], 1, tid);
    load_tile_async(sb + (1 % 3) * STAGE_BYTES + OFF_B, g_f16, tj0[0], 1, tid);
    CP_ASYNC_COMMIT();

    float acc[4][4][4];
#pragma unroll
    for (int mf = 0; mf < 4; ++mf)
#pragma unroll
        for (int nf = 0; nf < 4; ++nf)
#pragma unroll
            for (int q = 0; q < 4; ++q) acc[mf][nf][q] = 0.f;

    for (int g = 0; g < 8; ++g) {
        if (g < 7) { CP_ASYNC_WAIT(1); } else { CP_ASYNC_WAIT(0); }
        __syncthreads();                      // chunk g ready

        if (g + 2 < 8) {                      // prefetch into stage retired at g-1
            int gn = g + 2;
            uint32_t stn = sb + (gn % 3) * STAGE_BYTES;
            load_tile_async(stn + OFF_A, g_f16, ti0[gn >> 2], gn & 3, tid);
            load_tile_async(stn + OFF_B, g_f16, tj0[gn >> 2], gn & 3, tid);
            CP_ASYNC_COMMIT();
        }

        const uint32_t stb = sb + (g % 3) * STAGE_BYTES;
        const uint32_t aBase = stb + OFF_A;
        const uint32_t bBase = stb + OFF_B;
#pragma unroll
        for (int ks = 0; ks < 4; ++ks) {
            // B first: both 16-col fragments for this k-step (8 regs live)
            uint32_t bh0[4], bh1[4];
            {
                uint32_t boff0 = SMEM_SWIZZLE_128B(b_row_part + (uint32_t)(ks * 32));
                uint32_t boff1 = SMEM_SWIZZLE_128B(b_row_part + (uint32_t)(16 * 128) + (uint32_t)(ks * 32));
                LDSM_X4(bh0[0], bh0[1], bh0[2], bh0[3], bBase + boff0);
                LDSM_X4(bh1[0], bh1[1], bh1[2], bh1[3], bBase + boff1);
            }
            // A streamed: one fragment at a time, MMAs immediately follow
#pragma unroll
            for (int mf = 0; mf < 4; ++mf) {
                uint32_t ah[4];
                uint32_t aoff = SMEM_SWIZZLE_128B(a_row_part + (uint32_t)(mf * 16 * 128)
                                                  + (uint32_t)(ks * 32));
                LDSM_X4(ah[0], ah[1], ah[2], ah[3], aBase + aoff);
                MMA_F16(acc[mf][0], ah, bh0[0], bh0[1]);
                MMA_F16(acc[mf][1], ah, bh0[2], bh0[3]);
                MMA_F16(acc[mf][2], ah, bh1[0], bh1[1]);
                MMA_F16(acc[mf][3], ah, bh1[2], bh1[3]);
            }
        }

        if ((g & 3) == 3) {                   // tile complete -> epilogue
            int t = g >> 2;
            if (ti0[t] == tj0[t])
                tile_epilogue<true >(acc, ti0[t], tj0[t], wm, wn, lane, tid, sSr, sSc);
            else
                tile_epilogue<false>(acc, ti0[t], tj0[t], wm, wn, lane, tid, sSr, sSc);
#pragma unroll
            for (int mf = 0; mf < 4; ++mf)
#pragma unroll
                for (int nf = 0; nf < 4; ++nf)
#pragma unroll
                    for (int q = 0; q < 4; ++q) acc[mf][nf][q] = 0.f;
        }
    }

    // ---------------- Post-phase A: focal modulation (warp-per-sample) ----
    {
        int b = blockIdx.x * 8 + w;        // 2112 warps cover 2048 samples
        if (b < BB) {
            const float4* row4 = reinterpret_cast<const float4*>(preds + (size_t)b * CC);
            float s = 0.f;
#pragma unroll
            for (int k = 0; k < 8; ++k) {
                int idx = lane + 32 * k;
                if (idx < CC / 4) {
                    float4 v = row4[idx];
                    s += __expf(v.x) + __expf(v.y) + __expf(v.z) + __expf(v.w);
                }
            }
#pragma unroll
            for (int o = 16; o > 0; o >>= 1) s += __shfl_xor_sync(0xffffffffu, s, o);
            if (lane == 0) {
                float pl = preds[(size_t)b * CC + labels[b]];
                float pt = __expf(pl) / s;
                float om = 1.f - pt;
                g_mod[b] = om * om;
            }
        }
    }

    // ---------------- Post-phase B: zpk (class sums -> P, cnt) ----------
    for (int c = blockIdx.x; c < CC; c += MGRID) {
        __syncthreads();
        if (tid == 0) zm = 0;
        __syncthreads();
        for (int b = tid; b < BB; b += 256)
            if (labels[b] == c) { int p = atomicAdd(&zm, 1); if (p < 64) zlist[p] = b; }
        __syncthreads();
        const int mm = zm < 64 ? zm : 64;

        float z = 0.f;
        for (int q = 0; q < mm; ++q) {
            int b = zlist[q];
            z += __half2float(g_f16[(size_t)b * DD + tid])
               + __half2float(g_f16[(size_t)(BB + b) * DD + tid]);
        }
        Z[tid] = z;
        __syncthreads();

        const float cnt = 2.f * (float)zm - 1.f;
        for (int r = w; r < 2 * mm; r += 8) {
            int b = zlist[r >> 1];
            int row = (r & 1) ? (BB + b) : b;
            const __half2* hp = reinterpret_cast<const __half2*>(g_f16 + (size_t)row * DD);
            const float2*  zp = reinterpret_cast<const float2*>(Z);
            float dot = 0.f, self = 0.f;
#pragma unroll
            for (int k = 0; k < 4; ++k) {
                float2 hv = __half22float2(hp[lane + 32 * k]);
                float2 zv = zp[lane + 32 * k];
                dot  += hv.x * zv.x + hv.y * zv.y;
                self += hv.x * hv.x + hv.y * hv.y;
            }
#pragma unroll
            for (int o = 16; o > 0; o >>= 1) {
                dot  += __shfl_xor_sync(0xffffffffu, dot, o);
                self += __shfl_xor_sync(0xffffffffu, self, o);
            }
            if (lane == 0) {
                g_P[row]   = (dot - self - cnt) * invT;
                g_cnt[row] = cnt;
            }
        }
    }

    // ---------------- Fused finalize (last block) ----------------
    __threadfence();
    __syncthreads();
    if (tid == 0) isLast = (atomicAdd(&g_done, 1u) == MGRID - 1) ? 1u : 0u;
    __syncthreads();
    if (isLast) {
        __threadfence();
        float accv = 0.f;
        for (int i = tid; i < NN; i += 256) {
            float Sv = __ldcg(&g_S[i]);
            float Pv = __ldcg(&g_P[i]);
            float Cv = __ldcg(&g_cnt[i]);
            float mv = __ldcg(&g_mod[i & (BB - 1)]);
            accv += mv * (Pv / Cv - logf(Sv));
        }
        red[tid] = accv;
        __syncthreads();
#pragma unroll
        for (int s = 128; s > 0; s >>= 1) {
            if (tid < s) red[tid] += red[tid + s];
            __syncthreads();
        }
        if (tid == 0) { out[0] = -red[0] / (float)NN; g_done = 0u; }
    }
}

// ---------------------------------------------------------------------------
extern "C" void kernel_launch(void* const* d_in, const int* in_sizes, int n_in,
                              void* d_out, int out_size) {
    const float* feats  = (const float*)d_in[0];   // [B, V, D]
    const float* preds  = (const float*)d_in[1];   // [B, C]
    const int*   labels = (const int*)d_in[2];     // [B]
    float* out = (float*)d_out;

    cudaFuncSetAttribute(main_kernel, cudaFuncAttributeMaxDynamicSharedMemorySize, DYN_SMEM);

    norm_kernel<<<512, 256>>>(feats);
    main_kernel<<<MGRID, 256, DYN_SMEM>>>(preds, labels, out);
}